// round 13
// baseline (speedup 1.0000x reference)
#include <cuda_runtime.h>
#include <cstdint>

#define BB 4
#define CC 512
#define KK 64
#define NN 1024
#define NT 32   // k2 n-tile

typedef unsigned long long ull;

// ---- scratch (static __device__, no allocations) ----
__device__ __align__(16) float g_inv[KK * CC];    // [k][c]
__device__ __align__(16) float g_inv2t[CC * KK];  // [c][k]
__device__ __align__(16) float g_m2t[CC * KK];    // [c][k]
__device__ __align__(16) float g_ck[KK];
__device__ __align__(16) float g_wpart[(NN / NT) * BB * KK];  // [(nb*BB+b)*KK+k]
__device__ __align__(16) float g_part[4 * BB * KK * CC];      // 4 n-splits

// ---- f32x2 helpers ----
__device__ __forceinline__ ull pack2(float x, float y) {
    ull r; asm("mov.b64 %0, {%1,%2};" : "=l"(r) : "f"(x), "f"(y)); return r;
}
__device__ __forceinline__ ull fma2(ull a, ull b, ull c) {
    ull d; asm("fma.rn.f32x2 %0, %1, %2, %3;" : "=l"(d) : "l"(a), "l"(b), "l"(c)); return d;
}
__device__ __forceinline__ float2 unpack2(ull v) {
    float2 f; asm("mov.b64 {%0,%1}, %2;" : "=f"(f.x), "=f"(f.y) : "l"(v)); return f;
}

// ---- cp.async helpers ----
__device__ __forceinline__ void cp_async16(void* smem_dst, const void* gsrc) {
    unsigned sa = (unsigned)__cvta_generic_to_shared(smem_dst);
    asm volatile("cp.async.cg.shared.global [%0], [%1], 16;\n" :: "r"(sa), "l"(gsrc));
}
__device__ __forceinline__ void cp_commit() { asm volatile("cp.async.commit_group;\n"); }
template <int N>
__device__ __forceinline__ void cp_wait() { asm volatile("cp.async.wait_group %0;\n" :: "n"(N)); }

// ------------------------------------------------------------------
// Kernel 1: precompute per-(k,c) quantities + per-k constant (proven)
// ------------------------------------------------------------------
__global__ __launch_bounds__(256) void k1_prep(const float* __restrict__ anchor,
                                               const float* __restrict__ sp) {
    const int k = blockIdx.x;
    const int tid = threadIdx.x;
    float cks = 0.f;
#pragma unroll
    for (int r = 0; r < CC / 256; r++) {
        const int c = tid + r * 256;
        const float s = 1.f / (1.f + __expf(-sp[k * CC + c]));
        const float inv = __fdividef(1.f, s + 1e-7f);
        const float inv2 = inv * inv;
        const float a = anchor[k * CC + c];
        g_inv[k * CC + c] = inv;
        g_inv2t[c * KK + k] = inv2;
        g_m2t[c * KK + k] = -2.f * a * inv2;
        cks += a * a * inv2;
    }
    __shared__ float red[8];
    float v = cks;
#pragma unroll
    for (int o = 16; o > 0; o >>= 1) v += __shfl_xor_sync(0xffffffffu, v, o);
    if ((tid & 31) == 0) red[tid >> 5] = v;
    __syncthreads();
    if (tid == 0) {
        float s = 0.f;
#pragma unroll
        for (int w = 0; w < 8; w++) s += red[w];
        g_ck[k] = s;
    }
}

// ------------------------------------------------------------------
// Kernel 2: d2 GEMM (64k x 32n, inner C=512) + fused softmax over K
// 256 threads, grid (NN/32, BB) = 128 blocks. Thread tile 4k x 2n.
// 3-buffer cp.async ring, ONE __syncthreads per chunk.
// Warp-shuffle parallel softmax (8 warps x 4 columns) + coalesced stores.
// ------------------------------------------------------------------
__global__ __launch_bounds__(256) void k2_d2_softmax(const float* __restrict__ x,
                                                     float* __restrict__ soft_out) {
    const int b = blockIdx.y;
    const int nb = blockIdx.x;
    const int n0 = nb * NT;
    const int tid = threadIdx.x;
    const int tk = tid >> 4;  // 0..15 -> k base tk*4
    const int tn = tid & 15;  // 0..15 -> n base tn*2

    __shared__ __align__(16) float Wis[3][16 * 64];
    __shared__ __align__(16) float M2s[3][16 * 64];
    __shared__ __align__(16) float Xs[3][16 * NT];
    __shared__ float S[64 * 33];

    const float* xb = x + (size_t)b * CC * NN;

    auto issue = [&](int chunk, int buf) {
        const int c0 = chunk * 16;
        cp_async16(&Wis[buf][tid * 4], g_inv2t + c0 * KK + tid * 4);
        cp_async16(&M2s[buf][tid * 4], g_m2t + c0 * KK + tid * 4);
        if (tid < 128) {
            const int cc = tid >> 3, nn4 = (tid & 7) * 4;
            cp_async16(&Xs[buf][cc * NT + nn4], xb + (size_t)(c0 + cc) * NN + n0 + nn4);
        }
        cp_commit();
    };

    ull acc[2][2];
#pragma unroll
    for (int i = 0; i < 2; i++)
#pragma unroll
        for (int j = 0; j < 2; j++) acc[i][j] = 0ull;

    issue(0, 0);
    issue(1, 1);
    for (int ch = 0; ch < 32; ch++) {
        cp_wait<1>();
        __syncthreads();
        const int buf = ch - (ch / 3) * 3;  // ch % 3
        const float* Wb = Wis[buf];
        const float* Mb = M2s[buf];
        const float* Xb = Xs[buf];
#pragma unroll
        for (int cc = 0; cc < 16; cc++) {
            const ulonglong2 wp = *reinterpret_cast<const ulonglong2*>(Wb + cc * 64 + tk * 4);
            const ulonglong2 mp = *reinterpret_cast<const ulonglong2*>(Mb + cc * 64 + tk * 4);
            const float2 xv = *reinterpret_cast<const float2*>(Xb + cc * NT + tn * 2);
            const ull xd0 = pack2(xv.x, xv.x);
            const ull xd1 = pack2(xv.y, xv.y);
            ull t;
            t = fma2(wp.x, xd0, mp.x); acc[0][0] = fma2(t, xd0, acc[0][0]);
            t = fma2(wp.x, xd1, mp.x); acc[0][1] = fma2(t, xd1, acc[0][1]);
            t = fma2(wp.y, xd0, mp.y); acc[1][0] = fma2(t, xd0, acc[1][0]);
            t = fma2(wp.y, xd1, mp.y); acc[1][1] = fma2(t, xd1, acc[1][1]);
        }
        if (ch + 2 < 32) {
            const int nb2 = (ch + 2) - ((ch + 2) / 3) * 3;
            issue(ch + 2, nb2);
        }
    }

    // logits -> S (pad 33)
    {
        const int k0 = tk * 4;
#pragma unroll
        for (int kp = 0; kp < 2; kp++)
#pragma unroll
            for (int j = 0; j < 2; j++) {
                const float2 v = unpack2(acc[kp][j]);
                const int kk = k0 + kp * 2;
                const int n = tn * 2 + j;
                S[kk * 33 + n] = -0.5f * (v.x + g_ck[kk]);
                S[(kk + 1) * 33 + n] = -0.5f * (v.y + g_ck[kk + 1]);
            }
    }
    __syncthreads();

    // warp-shuffle parallel softmax: warp w owns columns w*4..w*4+3,
    // lane holds k = lane and lane+32. No extra block syncs.
    {
        const int lane = tid & 31;
        const int w = tid >> 5;
#pragma unroll
        for (int j = 0; j < 4; j++) {
            const int n = w * 4 + j;
            const float v0 = S[lane * 33 + n];
            const float v1 = S[(lane + 32) * 33 + n];
            float m = fmaxf(v0, v1);
#pragma unroll
            for (int o = 16; o > 0; o >>= 1) m = fmaxf(m, __shfl_xor_sync(0xffffffffu, m, o));
            const float e0 = __expf(v0 - m);
            const float e1 = __expf(v1 - m);
            float s = e0 + e1;
#pragma unroll
            for (int o = 16; o > 0; o >>= 1) s += __shfl_xor_sync(0xffffffffu, s, o);
            const float invs = 1.f / s;
            S[lane * 33 + n] = e0 * invs;
            S[(lane + 32) * 33 + n] = e1 * invs;
        }
    }
    __syncthreads();

    // coalesced global stores of probs (8 iters, 128B per warp-row)
    {
        float* outp = soft_out + (size_t)b * KK * NN + n0;
#pragma unroll
        for (int r = 0; r < 8; r++) {
            const int idx = tid + r * 256;   // 0..2047
            const int k = idx >> 5;
            const int n = idx & 31;
            outp[(size_t)k * NN + n] = S[k * 33 + n];
        }
    }

    // per-block wsum partials (threads 0..63, one per k)
    if (tid < 64) {
        float s = 0.f;
#pragma unroll
        for (int n = 0; n < NT; n++) s += S[tid * 33 + n];
        g_wpart[(nb * BB + b) * KK + tid] = s;
    }
}

// ------------------------------------------------------------------
// Kernel 3: num[b,k,c] = sum_n A[b,k,n]*x[b,c,n], split-N=4 partials
// grid (16 c-tiles, BB, 4 ns) = 256 blocks, 256 threads.
// X stored in shared as duplicated (x,x) ull pairs -> inner loop is
// 2x LDS.128 + 4 fma2 = 6 issues vs 8 fma-cycles (fma-bound).
// Register-prefetch double buffer, ONE __syncthreads per n-chunk.
// ------------------------------------------------------------------
__global__ __launch_bounds__(256) void k3_num(const float* __restrict__ soft,
                                              const float* __restrict__ x) {
    const int b = blockIdx.y;
    const int c0 = blockIdx.x * 32;
    const int ns = blockIdx.z;
    const int nbeg = ns * (NN / 4);

    __shared__ __align__(16) float As[2][16 * 68];  // [nn][k], pad 68
    __shared__ __align__(16) ull Xd[2][16 * 36];    // [nn][c-local] duplicated pairs

    const int tid = threadIdx.x;
    const int tc = tid & 15;   // c pair base = tc*2
    const int tk = tid >> 4;   // k base = tk*4 (two packed pairs)
    const int lrow = tid >> 4; // load row base (0..15)
    const int lnn = tid & 15;  // load nn

    ull acc[2][2];  // [kp][cj]
#pragma unroll
    for (int i = 0; i < 2; i++) { acc[i][0] = 0ull; acc[i][1] = 0ull; }

    const float* Ab = soft + (size_t)b * KK * NN;
    const float* xb = x + (size_t)b * CC * NN;

    // prologue: load + store iter 0 into buf 0
    {
        const int n0 = nbeg;
#pragma unroll
        for (int r = 0; r < 4; r++) {
            const int row = lrow + r * 16;  // 0..63 (k)
            As[0][lnn * 68 + row] = Ab[(size_t)row * NN + n0 + lnn];
        }
#pragma unroll
        for (int r = 0; r < 2; r++) {
            const int row = lrow + r * 16;  // 0..31 (c-local)
            const float v = xb[(size_t)(c0 + row) * NN + n0 + lnn];
            Xd[0][lnn * 36 + row] = pack2(v, v);
        }
    }

    for (int it = 0; it < 16; it++) {
        float aR[4], xR[2];
        const bool more = (it + 1 < 16);
        if (more) {
            const int n0 = nbeg + (it + 1) * 16;
#pragma unroll
            for (int r = 0; r < 4; r++)
                aR[r] = Ab[(size_t)(lrow + r * 16) * NN + n0 + lnn];
#pragma unroll
            for (int r = 0; r < 2; r++)
                xR[r] = xb[(size_t)(c0 + lrow + r * 16) * NN + n0 + lnn];
        }
        __syncthreads();
        const float* Ac = As[it & 1];
        const ull* Xc = Xd[it & 1];
#pragma unroll
        for (int nn = 0; nn < 16; nn++) {
            const ulonglong2 ap = *reinterpret_cast<const ulonglong2*>(&Ac[nn * 68 + tk * 4]);
            const ulonglong2 xp = *reinterpret_cast<const ulonglong2*>(&Xc[nn * 36 + tc * 2]);
            acc[0][0] = fma2(ap.x, xp.x, acc[0][0]);
            acc[0][1] = fma2(ap.x, xp.y, acc[0][1]);
            acc[1][0] = fma2(ap.y, xp.x, acc[1][0]);
            acc[1][1] = fma2(ap.y, xp.y, acc[1][1]);
        }
        if (more) {
            float* An = As[(it + 1) & 1];
            ull* Xn = Xd[(it + 1) & 1];
#pragma unroll
            for (int r = 0; r < 4; r++)
                An[lnn * 68 + lrow + r * 16] = aR[r];
#pragma unroll
            for (int r = 0; r < 2; r++)
                Xn[lnn * 36 + lrow + r * 16] = pack2(xR[r], xR[r]);
        }
    }

    float* P = g_part + ((size_t)ns * BB + b) * KK * CC;
#pragma unroll
    for (int kp = 0; kp < 2; kp++)
#pragma unroll
        for (int cj = 0; cj < 2; cj++) {
            const float2 v = unpack2(acc[kp][cj]);  // (k, k+1) for one c
            const int kg = tk * 4 + kp * 2;
            const int cg = c0 + tc * 2 + cj;
            P[(size_t)kg * CC + cg] = v.x;
            P[(size_t)(kg + 1) * CC + cg] = v.y;
        }
}

// ------------------------------------------------------------------
// Kernel 4: epilogue per (b,k): combine partials, subtract, scale,
// row-normalize, exact flat factor 1/8. (proven body)
// ------------------------------------------------------------------
__global__ __launch_bounds__(128) void k4_nodes(const float* __restrict__ anchor,
                                                float* __restrict__ nodes_out) {
    const int k = blockIdx.x;
    const int b = blockIdx.y;
    const int tid = threadIdx.x;

    __shared__ float redw[1];
    __shared__ float red[4];
    __shared__ float rfs;

    // issue ALL independent loads first (max MLP)
    float wv = 0.f;
    if (tid < 32) wv = g_wpart[(tid * BB + b) * KK + k];
    const int c = tid * 4;
    float4 p0 = *reinterpret_cast<const float4*>(&g_part[((size_t)0 * BB + b) * KK * CC + (size_t)k * CC + c]);
    float4 p1 = *reinterpret_cast<const float4*>(&g_part[((size_t)1 * BB + b) * KK * CC + (size_t)k * CC + c]);
    float4 p2 = *reinterpret_cast<const float4*>(&g_part[((size_t)2 * BB + b) * KK * CC + (size_t)k * CC + c]);
    float4 p3 = *reinterpret_cast<const float4*>(&g_part[((size_t)3 * BB + b) * KK * CC + (size_t)k * CC + c]);
    const float4 a = *reinterpret_cast<const float4*>(&anchor[k * CC + c]);
    const float4 iv = *reinterpret_cast<const float4*>(&g_inv[k * CC + c]);

    if (tid < 32) {
#pragma unroll
        for (int o = 16; o > 0; o >>= 1) wv += __shfl_xor_sync(0xffffffffu, wv, o);
        if (tid == 0) redw[0] = wv;
    }
    __syncthreads();
    const float w = redw[0];
    const float invden = 1.f / (w + 1e-7f);

    float4 s;
    s.x = (p0.x + p1.x) + (p2.x + p3.x);
    s.y = (p0.y + p1.y) + (p2.y + p3.y);
    s.z = (p0.z + p1.z) + (p2.z + p3.z);
    s.w = (p0.w + p1.w) + (p2.w + p3.w);
    float4 v;
    v.x = (s.x - w * a.x) * iv.x * invden;
    v.y = (s.y - w * a.y) * iv.y * invden;
    v.z = (s.z - w * a.z) * iv.z * invden;
    v.w = (s.w - w * a.w) * iv.w * invden;

    float ss = v.x * v.x + v.y * v.y + v.z * v.z + v.w * v.w;
#pragma unroll
    for (int o = 16; o > 0; o >>= 1) ss += __shfl_xor_sync(0xffffffffu, ss, o);
    if ((tid & 31) == 0) red[tid >> 5] = ss;
    __syncthreads();
    if (tid == 0) {
        const float sumsq = red[0] + red[1] + red[2] + red[3];
        rfs = 0.125f / fmaxf(sqrtf(sumsq), 1e-12f);  // row norm * 1/sqrt(K)
    }
    __syncthreads();
    const float rf = rfs;
    float4 o4;
    o4.x = v.x * rf; o4.y = v.y * rf; o4.z = v.z * rf; o4.w = v.w * rf;
    *reinterpret_cast<float4*>(&nodes_out[((size_t)b * KK + k) * CC + c]) = o4;
}

// ------------------------------------------------------------------
extern "C" void kernel_launch(void* const* d_in, const int* in_sizes, int n_in,
                              void* d_out, int out_size) {
    (void)in_sizes; (void)n_in; (void)out_size;
    const float* x = (const float*)d_in[0];       // (4,512,32,32)
    const float* anchor = (const float*)d_in[1];  // (64,512)
    const float* sp = (const float*)d_in[2];      // (64,512)
    float* out = (float*)d_out;
    float* nodes_out = out;                        // B*K*C (viewed (B,C,K))
    float* soft_out = out + (size_t)BB * KK * CC;  // B*K*N

    k1_prep<<<KK, 256>>>(anchor, sp);
    k2_d2_softmax<<<dim3(NN / NT, BB), 256>>>(x, soft_out);
    k3_num<<<dim3(16, BB, 4), 256>>>(soft_out, x);
    k4_nodes<<<dim3(KK, BB), 128>>>(anchor, nodes_out);
}

// round 15
// speedup vs baseline: 1.1822x; 1.1822x over previous
#include <cuda_runtime.h>
#include <cstdint>

#define BB 4
#define CC 512
#define KK 64
#define NN 1024
#define NT 32   // k2 n-tile

typedef unsigned long long ull;

// ---- scratch (static __device__, no allocations) ----
__device__ __align__(16) float g_inv[KK * CC];    // [k][c]
__device__ __align__(16) float g_inv2t[CC * KK];  // [c][k]
__device__ __align__(16) float g_m2t[CC * KK];    // [c][k]
__device__ __align__(16) float g_ck[KK];
__device__ __align__(16) float g_wpart[(NN / NT) * BB * KK];  // [(nb*BB+b)*KK+k]
__device__ __align__(16) float g_part[4 * BB * KK * CC];      // 4 n-splits

// ---- f32x2 helpers ----
__device__ __forceinline__ ull pack2(float x, float y) {
    ull r; asm("mov.b64 %0, {%1,%2};" : "=l"(r) : "f"(x), "f"(y)); return r;
}
__device__ __forceinline__ ull fma2(ull a, ull b, ull c) {
    ull d; asm("fma.rn.f32x2 %0, %1, %2, %3;" : "=l"(d) : "l"(a), "l"(b), "l"(c)); return d;
}
__device__ __forceinline__ float2 unpack2(ull v) {
    float2 f; asm("mov.b64 {%0,%1}, %2;" : "=f"(f.x), "=f"(f.y) : "l"(v)); return f;
}

// ---- cp.async helpers ----
__device__ __forceinline__ void cp_async16(void* smem_dst, const void* gsrc) {
    unsigned sa = (unsigned)__cvta_generic_to_shared(smem_dst);
    asm volatile("cp.async.cg.shared.global [%0], [%1], 16;\n" :: "r"(sa), "l"(gsrc));
}
__device__ __forceinline__ void cp_commit() { asm volatile("cp.async.commit_group;\n"); }
template <int N>
__device__ __forceinline__ void cp_wait() { asm volatile("cp.async.wait_group %0;\n" :: "n"(N)); }

// ------------------------------------------------------------------
// Kernel 1: precompute per-(k,c) quantities + per-k constant (proven)
// ------------------------------------------------------------------
__global__ __launch_bounds__(256) void k1_prep(const float* __restrict__ anchor,
                                               const float* __restrict__ sp) {
    const int k = blockIdx.x;
    const int tid = threadIdx.x;
    float cks = 0.f;
#pragma unroll
    for (int r = 0; r < CC / 256; r++) {
        const int c = tid + r * 256;
        const float s = 1.f / (1.f + __expf(-sp[k * CC + c]));
        const float inv = __fdividef(1.f, s + 1e-7f);
        const float inv2 = inv * inv;
        const float a = anchor[k * CC + c];
        g_inv[k * CC + c] = inv;
        g_inv2t[c * KK + k] = inv2;
        g_m2t[c * KK + k] = -2.f * a * inv2;
        cks += a * a * inv2;
    }
    __shared__ float red[8];
    float v = cks;
#pragma unroll
    for (int o = 16; o > 0; o >>= 1) v += __shfl_xor_sync(0xffffffffu, v, o);
    if ((tid & 31) == 0) red[tid >> 5] = v;
    __syncthreads();
    if (tid == 0) {
        float s = 0.f;
#pragma unroll
        for (int w = 0; w < 8; w++) s += red[w];
        g_ck[k] = s;
    }
}

// ------------------------------------------------------------------
// Kernel 2: d2 GEMM (64k x 32n, inner C=512) + fused softmax over K
// 256 threads, grid (NN/32, BB) = 128 blocks. Thread tile 4k x 2n.
// 3-buffer cp.async ring, ONE __syncthreads per chunk. (proven R12)
// ------------------------------------------------------------------
__global__ __launch_bounds__(256) void k2_d2_softmax(const float* __restrict__ x,
                                                     float* __restrict__ soft_out) {
    const int b = blockIdx.y;
    const int nb = blockIdx.x;
    const int n0 = nb * NT;
    const int tid = threadIdx.x;
    const int tk = tid >> 4;  // 0..15 -> k base tk*4
    const int tn = tid & 15;  // 0..15 -> n base tn*2

    __shared__ __align__(16) float Wis[3][16 * 64];
    __shared__ __align__(16) float M2s[3][16 * 64];
    __shared__ __align__(16) float Xs[3][16 * NT];
    __shared__ float S[64 * 33];

    const float* xb = x + (size_t)b * CC * NN;

    auto issue = [&](int chunk, int buf) {
        const int c0 = chunk * 16;
        cp_async16(&Wis[buf][tid * 4], g_inv2t + c0 * KK + tid * 4);
        cp_async16(&M2s[buf][tid * 4], g_m2t + c0 * KK + tid * 4);
        if (tid < 128) {
            const int cc = tid >> 3, nn4 = (tid & 7) * 4;
            cp_async16(&Xs[buf][cc * NT + nn4], xb + (size_t)(c0 + cc) * NN + n0 + nn4);
        }
        cp_commit();
    };

    ull acc[2][2];
#pragma unroll
    for (int i = 0; i < 2; i++)
#pragma unroll
        for (int j = 0; j < 2; j++) acc[i][j] = 0ull;

    issue(0, 0);
    issue(1, 1);
    for (int ch = 0; ch < 32; ch++) {
        cp_wait<1>();
        __syncthreads();
        const int buf = ch - (ch / 3) * 3;  // ch % 3
        const float* Wb = Wis[buf];
        const float* Mb = M2s[buf];
        const float* Xb = Xs[buf];
#pragma unroll
        for (int cc = 0; cc < 16; cc++) {
            const ulonglong2 wp = *reinterpret_cast<const ulonglong2*>(Wb + cc * 64 + tk * 4);
            const ulonglong2 mp = *reinterpret_cast<const ulonglong2*>(Mb + cc * 64 + tk * 4);
            const float2 xv = *reinterpret_cast<const float2*>(Xb + cc * NT + tn * 2);
            const ull xd0 = pack2(xv.x, xv.x);
            const ull xd1 = pack2(xv.y, xv.y);
            ull t;
            t = fma2(wp.x, xd0, mp.x); acc[0][0] = fma2(t, xd0, acc[0][0]);
            t = fma2(wp.x, xd1, mp.x); acc[0][1] = fma2(t, xd1, acc[0][1]);
            t = fma2(wp.y, xd0, mp.y); acc[1][0] = fma2(t, xd0, acc[1][0]);
            t = fma2(wp.y, xd1, mp.y); acc[1][1] = fma2(t, xd1, acc[1][1]);
        }
        if (ch + 2 < 32) {
            const int nb2 = (ch + 2) - ((ch + 2) / 3) * 3;
            issue(ch + 2, nb2);
        }
    }

    // logits -> S (pad 33)
    {
        const int k0 = tk * 4;
#pragma unroll
        for (int kp = 0; kp < 2; kp++)
#pragma unroll
            for (int j = 0; j < 2; j++) {
                const float2 v = unpack2(acc[kp][j]);
                const int kk = k0 + kp * 2;
                const int n = tn * 2 + j;
                S[kk * 33 + n] = -0.5f * (v.x + g_ck[kk]);
                S[(kk + 1) * 33 + n] = -0.5f * (v.y + g_ck[kk + 1]);
            }
    }
    __syncthreads();

    // serial softmax per column (threads 0..31) — proven shape
    if (tid < NT) {
        const int n = tid;
        float m = -1e30f;
#pragma unroll
        for (int k = 0; k < KK; k++) m = fmaxf(m, S[k * 33 + n]);
        float s = 0.f;
#pragma unroll
        for (int k = 0; k < KK; k++) s += __expf(S[k * 33 + n] - m);
        const float invs = 1.f / s;
        float* outp = soft_out + (size_t)b * KK * NN + n0 + n;
#pragma unroll
        for (int k = 0; k < KK; k++) {
            const float p = __expf(S[k * 33 + n] - m) * invs;
            S[k * 33 + n] = p;
            outp[(size_t)k * NN] = p;
        }
    }
    __syncthreads();

    // per-block wsum partials (threads 0..63, one per k)
    if (tid < 64) {
        float s = 0.f;
#pragma unroll
        for (int n = 0; n < NT; n++) s += S[tid * 33 + n];
        g_wpart[(nb * BB + b) * KK + tid] = s;
    }
}

// ------------------------------------------------------------------
// Kernel 3: num[b,k,c] = sum_n A[b,k,n]*x[b,c,n], split-N=4 partials
// grid (16 c-tiles, BB, 4 ns) = 256 blocks, 256 threads.
// Register-prefetch double buffer, ONE __syncthreads per n-chunk. (proven R12)
// ------------------------------------------------------------------
__global__ __launch_bounds__(256) void k3_num(const float* __restrict__ soft,
                                              const float* __restrict__ x) {
    const int b = blockIdx.y;
    const int c0 = blockIdx.x * 32;
    const int ns = blockIdx.z;
    const int nbeg = ns * (NN / 4);

    __shared__ __align__(16) float As[2][16 * 68];  // [nn][k], pad 68
    __shared__ __align__(16) float Xs[2][16 * 36];  // [nn][c-local], pad 36

    const int tid = threadIdx.x;
    const int tc = tid & 15;   // c pair base = tc*2
    const int tk = tid >> 4;   // k base = tk*4 (two packed pairs)
    const int lrow = tid >> 4; // load row base (0..15)
    const int lnn = tid & 15;  // load nn

    ull acc[2][2];  // [kp][cj]
#pragma unroll
    for (int i = 0; i < 2; i++) { acc[i][0] = 0ull; acc[i][1] = 0ull; }

    const float* Ab = soft + (size_t)b * KK * NN;
    const float* xb = x + (size_t)b * CC * NN;

    // prologue: load + store iter 0 into buf 0
    {
        const int n0 = nbeg;
#pragma unroll
        for (int r = 0; r < 4; r++) {
            const int row = lrow + r * 16;  // 0..63 (k)
            As[0][lnn * 68 + row] = Ab[(size_t)row * NN + n0 + lnn];
        }
#pragma unroll
        for (int r = 0; r < 2; r++) {
            const int row = lrow + r * 16;  // 0..31 (c-local)
            Xs[0][lnn * 36 + row] = xb[(size_t)(c0 + row) * NN + n0 + lnn];
        }
    }

    for (int it = 0; it < 16; it++) {
        float aR[4], xR[2];
        const bool more = (it + 1 < 16);
        if (more) {
            const int n0 = nbeg + (it + 1) * 16;
#pragma unroll
            for (int r = 0; r < 4; r++)
                aR[r] = Ab[(size_t)(lrow + r * 16) * NN + n0 + lnn];
#pragma unroll
            for (int r = 0; r < 2; r++)
                xR[r] = xb[(size_t)(c0 + lrow + r * 16) * NN + n0 + lnn];
        }
        __syncthreads();
        const float* Ac = As[it & 1];
        const float* Xc = Xs[it & 1];
#pragma unroll
        for (int nn = 0; nn < 16; nn++) {
            const ulonglong2 ap = *reinterpret_cast<const ulonglong2*>(&Ac[nn * 68 + tk * 4]);
            const float2 xv = *reinterpret_cast<const float2*>(&Xc[nn * 36 + tc * 2]);
            const ull xd0 = pack2(xv.x, xv.x);
            const ull xd1 = pack2(xv.y, xv.y);
            acc[0][0] = fma2(ap.x, xd0, acc[0][0]);
            acc[0][1] = fma2(ap.x, xd1, acc[0][1]);
            acc[1][0] = fma2(ap.y, xd0, acc[1][0]);
            acc[1][1] = fma2(ap.y, xd1, acc[1][1]);
        }
        if (more) {
            float* An = As[(it + 1) & 1];
            float* Xn = Xs[(it + 1) & 1];
#pragma unroll
            for (int r = 0; r < 4; r++)
                An[lnn * 68 + lrow + r * 16] = aR[r];
#pragma unroll
            for (int r = 0; r < 2; r++)
                Xn[lnn * 36 + lrow + r * 16] = xR[r];
        }
    }

    float* P = g_part + ((size_t)ns * BB + b) * KK * CC;
#pragma unroll
    for (int kp = 0; kp < 2; kp++)
#pragma unroll
        for (int cj = 0; cj < 2; cj++) {
            const float2 v = unpack2(acc[kp][cj]);  // (k, k+1) for one c
            const int kg = tk * 4 + kp * 2;
            const int cg = c0 + tc * 2 + cj;
            P[(size_t)kg * CC + cg] = v.x;
            P[(size_t)(kg + 1) * CC + cg] = v.y;
        }
}

// ------------------------------------------------------------------
// Kernel 4: epilogue, 2 (b,k) rows per block -> 128 blocks = 1 wave.
// 256 threads; halves (tid>>7) each own one row. (R9 phase-D structure)
// ------------------------------------------------------------------
__global__ __launch_bounds__(256) void k4_nodes(const float* __restrict__ anchor,
                                                float* __restrict__ nodes_out) {
    const int tid = threadIdx.x;
    const int blk = blockIdx.x;

    __shared__ float redw[2];
    __shared__ float red[8];
    __shared__ float rfs[2];

    const int h = tid >> 7;    // half 0/1
    const int ht = tid & 127;
    const int r = blk * 2 + h; // 0..255
    const int b = r >> 6, k = r & 63;

    // issue ALL independent loads first (max MLP)
    float wv = 0.f;
    if (ht < 32) wv = g_wpart[(ht * BB + b) * KK + k];
    const int c = ht * 4;
    const size_t base = (size_t)b * KK * CC + (size_t)k * CC + c;
    float4 p0 = *reinterpret_cast<const float4*>(&g_part[(size_t)0 * BB * KK * CC + base]);
    float4 p1 = *reinterpret_cast<const float4*>(&g_part[(size_t)1 * BB * KK * CC + base]);
    float4 p2 = *reinterpret_cast<const float4*>(&g_part[(size_t)2 * BB * KK * CC + base]);
    float4 p3 = *reinterpret_cast<const float4*>(&g_part[(size_t)3 * BB * KK * CC + base]);
    const float4 a = *reinterpret_cast<const float4*>(&anchor[k * CC + c]);
    const float4 iv = *reinterpret_cast<const float4*>(&g_inv[k * CC + c]);

    if (ht < 32) {
#pragma unroll
        for (int o = 16; o > 0; o >>= 1) wv += __shfl_xor_sync(0xffffffffu, wv, o);
        if (ht == 0) redw[h] = wv;
    }
    __syncthreads();
    const float w = redw[h];
    const float invden = 1.f / (w + 1e-7f);

    float4 s;
    s.x = (p0.x + p1.x) + (p2.x + p3.x);
    s.y = (p0.y + p1.y) + (p2.y + p3.y);
    s.z = (p0.z + p1.z) + (p2.z + p3.z);
    s.w = (p0.w + p1.w) + (p2.w + p3.w);
    float4 v;
    v.x = (s.x - w * a.x) * iv.x * invden;
    v.y = (s.y - w * a.y) * iv.y * invden;
    v.z = (s.z - w * a.z) * iv.z * invden;
    v.w = (s.w - w * a.w) * iv.w * invden;

    float ss = v.x * v.x + v.y * v.y + v.z * v.z + v.w * v.w;
#pragma unroll
    for (int o = 16; o > 0; o >>= 1) ss += __shfl_xor_sync(0xffffffffu, ss, o);
    if ((ht & 31) == 0) red[h * 4 + (ht >> 5)] = ss;
    __syncthreads();
    if (ht == 0) {
        const float sumsq = red[h * 4] + red[h * 4 + 1] + red[h * 4 + 2] + red[h * 4 + 3];
        rfs[h] = 0.125f / fmaxf(sqrtf(sumsq), 1e-12f);  // row norm * 1/sqrt(K)
    }
    __syncthreads();
    const float rf = rfs[h];
    float4 o4;
    o4.x = v.x * rf; o4.y = v.y * rf; o4.z = v.z * rf; o4.w = v.w * rf;
    *reinterpret_cast<float4*>(&nodes_out[((size_t)b * KK + k) * CC + c]) = o4;
}

// ------------------------------------------------------------------
extern "C" void kernel_launch(void* const* d_in, const int* in_sizes, int n_in,
                              void* d_out, int out_size) {
    (void)in_sizes; (void)n_in; (void)out_size;
    const float* x = (const float*)d_in[0];       // (4,512,32,32)
    const float* anchor = (const float*)d_in[1];  // (64,512)
    const float* sp = (const float*)d_in[2];      // (64,512)
    float* out = (float*)d_out;
    float* nodes_out = out;                        // B*K*C (viewed (B,C,K))
    float* soft_out = out + (size_t)BB * KK * CC;  // B*K*N

    k1_prep<<<KK, 256>>>(anchor, sp);
    k2_d2_softmax<<<dim3(NN / NT, BB), 256>>>(x, soft_out);
    k3_num<<<dim3(16, BB, 4), 256>>>(soft_out, x);
    k4_nodes<<<128, 256>>>(anchor, nodes_out);
}